// round 13
// baseline (speedup 1.0000x reference)
#include <cuda_runtime.h>
#include <cuda_fp16.h>
#include <cstdint>

// ============================ problem constants ============================
static constexpr int E_TOTAL = 500000;
static constexpr int MEM_D   = 100;
static constexpr int EDGE_D  = 172;
static constexpr int HID     = 128;
static constexpr int IN_D    = 472;   // 100 + 100 + 100 + 172
static constexpr int K_PAD   = 480;
static constexpr int KCHUNK  = 16;
static constexpr int NCHUNK  = K_PAD / KCHUNK;    // 30
static constexpr int TILE_M  = 256;               // edges per tile
static constexpr int NTHREADS = 512;              // 16 warps: 8 wm x 2 wn
static constexpr int NUM_CTAS = 152;              // persistent: one per SM
static constexpr int NUM_TILES = (E_TOTAL + TILE_M - 1) / TILE_M;  // 1954

static constexpr int B_LD  = 136;                 // halves; 272B row stride
static constexpr int A_LDF = 20;                  // floats per A row (16 + 4 pad) = 80B
static constexpr int NRING = 4;                   // A ring depth (3 chunks in flight)
static constexpr int A_CH_FLOATS = TILE_M * A_LDF;          // 5120 (20480 B/chunk)

// ============================ smem layout (bytes, dynamic) ============================
static constexpr int SO_B    = 0;
static constexpr int B_BYTES = K_PAD * B_LD * 2;            // 130560
static constexpr int SO_A    = SO_B + B_BYTES;
static constexpr int A_BYTES = NRING * A_CH_FLOATS * 4;     // 81920
static constexpr int SO_SRC  = SO_A + A_BYTES;              // int[256]
static constexpr int SO_DST  = SO_SRC + TILE_M * 4;
static constexpr int SO_EOF  = SO_DST + TILE_M * 4;
static constexpr int SO_DT   = SO_EOF + TILE_M * 4;         // float[256]
static constexpr int SO_B1   = SO_DT  + TILE_M * 4;         // float[128]
static constexpr int SO_W2   = SO_B1  + HID * 4;            // float[128]
static constexpr int SO_PART = SO_W2  + HID * 4;            // float[512]
static constexpr int SMEM_DYN = SO_PART + 2 * TILE_M * 4;   // 219648 B

// fp16 w1, row-major [K_PAD x HID], zero rows 472..479.
__device__ __align__(16) __half g_w1_f16[K_PAD * HID];

__device__ __forceinline__ uint32_t smem_u32(const void* p) {
    uint32_t a;
    asm("{ .reg .u64 t; cvta.to.shared.u64 t, %1; cvt.u32.u64 %0, t; }" : "=r"(a) : "l"(p));
    return a;
}

__device__ __forceinline__ void cpa8(uint32_t dst, const void* src) {
    asm volatile("cp.async.ca.shared.global [%0], [%1], 8;" :: "r"(dst), "l"(src) : "memory");
}

// Accurate cos for |x| up to ~1e4: Cody-Waite 2-step reduction + MUFU cos.
__device__ __forceinline__ float fast_cos(float x) {
    float k = rintf(x * 0.15915494309189535f);
    float y = fmaf(-k, 6.28125f, x);
    y = fmaf(-k, 1.9353072e-3f, y);
    return __cosf(y);
}

__device__ __forceinline__ void mma16816(float d[4], const uint32_t a[4],
                                         uint32_t b0, uint32_t b1) {
    asm volatile(
        "mma.sync.aligned.m16n8k16.row.col.f32.f16.f16.f32 "
        "{%0,%1,%2,%3}, {%4,%5,%6,%7}, {%8,%9}, {%0,%1,%2,%3};"
        : "+f"(d[0]), "+f"(d[1]), "+f"(d[2]), "+f"(d[3])
        : "r"(a[0]), "r"(a[1]), "r"(a[2]), "r"(a[3]), "r"(b0), "r"(b1));
}

// ============================ prologue: w1 -> fp16 ============================
__global__ void prep_w1_kernel(const float* __restrict__ w1) {
    int idx = blockIdx.x * blockDim.x + threadIdx.x;
    int k = idx / HID;
    float v = (k < IN_D) ? w1[idx] : 0.0f;
    g_w1_f16[idx] = __float2half(v);
}

// ============================ main kernel ============================
__global__ void __launch_bounds__(NTHREADS, 1)
tgn_growth_kernel(const int* __restrict__ src, const int* __restrict__ dst,
                  const float* __restrict__ t, const float* __restrict__ edge_attr,
                  const float* __restrict__ memory, const float* __restrict__ last_update,
                  const float* __restrict__ time_w, const float* __restrict__ time_b,
                  const float* __restrict__ b1, const float* __restrict__ w2,
                  const float* __restrict__ b2, float* __restrict__ out) {
    extern __shared__ __align__(16) char smem[];
    int*   sSrc = (int*)(smem + SO_SRC);
    int*   sDst = (int*)(smem + SO_DST);
    int*   sEof = (int*)(smem + SO_EOF);
    float* sDt  = (float*)(smem + SO_DT);
    float* sB1f = (float*)(smem + SO_B1);
    float* sW2f = (float*)(smem + SO_W2);
    float* sPart= (float*)(smem + SO_PART);
    float* sAf  = (float*)(smem + SO_A);

    const int tid = threadIdx.x;
    const int wid = tid >> 5;
    const int lid = tid & 31;
    const int wm  = wid >> 1;          // 0..7: rows [32wm, 32wm+32)
    const int wn  = wid & 1;           // 0..1: cols [64wn, 64wn+64)
    const int rl  = lid >> 2;          // 0..7
    const int c0  = (lid & 3) * 2;     // 0,2,4,6
    // staging role: thread owns k-pair jp for rows prow + {0,64,128,192}
    const int jp   = tid & 7;
    const int prow = tid >> 3;         // 0..63

    // ---- load full W1 into smem once ----
    const uint32_t bBase = smem_u32(smem + SO_B);
    for (int i = tid; i < K_PAD * 16; i += NTHREADS) {    // 480 rows x 16 16B-segs
        const int row = i >> 4, seg = i & 15;
        const __half* gsrc = g_w1_f16 + row * HID + seg * 8;
        asm volatile("cp.async.cg.shared.global [%0], [%1], 16;"
                     :: "r"(bBase + (uint32_t)(row * B_LD + seg * 8) * 2), "l"(gsrc)
                     : "memory");
    }
    asm volatile("cp.async.commit_group;" ::: "memory");
    if (tid < HID) { sB1f[tid] = b1[tid]; sW2f[tid] = w2[tid]; }
    const float bias2 = b2[0];
    asm volatile("cp.async.wait_group 0;" ::: "memory");
    __syncthreads();

    // ldmatrix.x4 lane address: lanes 0-15 -> 16 k-rows of col block, lanes 16-31 -> next 8 cols.
    const uint32_t ldmBase =
        bBase + (uint32_t)((((lid & 15) * B_LD) + wn * 64 + ((lid >> 4) * 8)) * 2);
    const uint32_t aRing = smem_u32(sAf);

    // ---- persistent tile loop ----
    for (int tile = blockIdx.x; tile < NUM_TILES; tile += NUM_CTAS) {
        const int tile0 = tile * TILE_M;

        __syncthreads();   // previous tile fully consumed (ring + sPart safe)
        if (tid < TILE_M) {
            int e  = tile0 + tid;
            int ec = (e < E_TOTAL) ? e : (E_TOTAL - 1);
            int s  = src[ec];
            sSrc[tid] = s * MEM_D;
            sDst[tid] = dst[ec] * MEM_D;
            sDt[tid]  = t[ec] - last_update[s];
            sEof[tid] = ec * EDGE_D;
        }
        __syncthreads();

        // staging-row offsets (rows prow + 64j)
        int pSrc[4], pDst[4], pEof[4];
        float pDt[4];
        #pragma unroll
        for (int j = 0; j < 4; ++j) {
            const int r = prow + 64 * j;
            pSrc[j] = sSrc[r]; pDst[j] = sDst[r]; pEof[j] = sEof[r]; pDt[j] = sDt[r];
        }

        // stage chunk c into ring slot c&3 (cp.async for copyable regions, STS for time/zero)
        auto stage = [&](int c) {
            const int slot = c & 3;
            const int k = c * KCHUNK + (jp << 1);        // uniform per thread
            const uint32_t dBase = aRing + (uint32_t)(slot * A_CH_FLOATS * 4);
            float* fBase = sAf + slot * A_CH_FLOATS;
            if (k >= 200 && k < 300) {                   // time encoding: compute + STS
                float2 tw2 = *reinterpret_cast<const float2*>(time_w + (k - 200));
                float2 tb2 = *reinterpret_cast<const float2*>(time_b + (k - 200));
                #pragma unroll
                for (int j = 0; j < 4; ++j) {
                    float2 v;
                    v.x = fast_cos(fmaf(pDt[j], tw2.x, tb2.x));
                    v.y = fast_cos(fmaf(pDt[j], tw2.y, tb2.y));
                    *reinterpret_cast<float2*>(fBase + (prow + 64 * j) * A_LDF + (jp << 1)) = v;
                }
            } else if (k >= IN_D) {                      // zero padding
                #pragma unroll
                for (int j = 0; j < 4; ++j)
                    *reinterpret_cast<float2*>(fBase + (prow + 64 * j) * A_LDF + (jp << 1)) =
                        make_float2(0.0f, 0.0f);
            } else {                                     // DMA regions
                #pragma unroll
                for (int j = 0; j < 4; ++j) {
                    const float* g;
                    if (k < MEM_D)        g = memory + pSrc[j] + k;
                    else if (k < 200)     g = memory + pDst[j] + (k - MEM_D);
                    else                  g = edge_attr + pEof[j] + (k - 300);
                    cpa8(dBase + (uint32_t)(((prow + 64 * j) * A_LDF + (jp << 1)) * 4), g);
                }
            }
            asm volatile("cp.async.commit_group;" ::: "memory");
        };

        float acc[2][8][4];
        #pragma unroll
        for (int mt = 0; mt < 2; ++mt)
            #pragma unroll
            for (int nt = 0; nt < 8; ++nt)
                #pragma unroll
                for (int q = 0; q < 4; ++q) acc[mt][nt][q] = 0.0f;

        stage(0); stage(1); stage(2);   // 3 chunks in flight

        #pragma unroll 2
        for (int c = 0; c < NCHUNK; ++c) {
            asm volatile("cp.async.wait_group 2;" ::: "memory");
            __syncthreads();            // chunk c visible to all warps

            // A fragments: LDS fp32 -> half2
            const float* a = sAf + (c & 3) * A_CH_FLOATS;
            uint32_t aR[2][4];
            #pragma unroll
            for (int mt = 0; mt < 2; ++mt)
                #pragma unroll
                for (int h = 0; h < 2; ++h)
                    #pragma unroll
                    for (int g = 0; g < 2; ++g) {
                        float2 v = *reinterpret_cast<const float2*>(
                            a + (wm * 32 + mt * 16 + h * 8 + rl) * A_LDF + c0 + g * 8);
                        __half2 h2 = __floats2half2_rn(v.x, v.y);
                        aR[mt][g * 2 + h] = *reinterpret_cast<uint32_t*>(&h2);
                    }

            // B via ldmatrix.x4 (2 n-tiles per instruction), then MMA
            const uint32_t la = ldmBase + (uint32_t)(c * KCHUNK * B_LD * 2);
            #pragma unroll
            for (int ntp = 0; ntp < 4; ++ntp) {
                uint32_t b0, b1r, b2r, b3r;
                asm volatile(
                    "ldmatrix.sync.aligned.m8n8.x4.trans.shared.b16 {%0,%1,%2,%3}, [%4];"
                    : "=r"(b0), "=r"(b1r), "=r"(b2r), "=r"(b3r) : "r"(la + ntp * 32));
                mma16816(acc[0][2 * ntp],     aR[0], b0, b1r);
                mma16816(acc[1][2 * ntp],     aR[1], b0, b1r);
                mma16816(acc[0][2 * ntp + 1], aR[0], b2r, b3r);
                mma16816(acc[1][2 * ntp + 1], aR[1], b2r, b3r);
            }

            // keep group count constant: real stage or empty commit
            if (c + 3 < NCHUNK) stage(c + 3);
            else asm volatile("cp.async.commit_group;" ::: "memory");
        }

        // ---- epilogue: bias + ReLU + dot(w2) in regs, shfl reduce ----
        #pragma unroll
        for (int mt = 0; mt < 2; ++mt) {
            float p1 = 0.0f, p2 = 0.0f;
            #pragma unroll
            for (int nt = 0; nt < 8; ++nt) {
                const int n0 = wn * 64 + nt * 8 + c0;
                float2 bb = *reinterpret_cast<const float2*>(&sB1f[n0]);
                float2 ww = *reinterpret_cast<const float2*>(&sW2f[n0]);
                const float* d = acc[mt][nt];
                p1 = fmaf(fmaxf(d[0] + bb.x, 0.0f), ww.x, p1);
                p1 = fmaf(fmaxf(d[1] + bb.y, 0.0f), ww.y, p1);
                p2 = fmaf(fmaxf(d[2] + bb.x, 0.0f), ww.x, p2);
                p2 = fmaf(fmaxf(d[3] + bb.y, 0.0f), ww.y, p2);
            }
            p1 += __shfl_xor_sync(0xFFFFFFFFu, p1, 1);
            p1 += __shfl_xor_sync(0xFFFFFFFFu, p1, 2);
            p2 += __shfl_xor_sync(0xFFFFFFFFu, p2, 1);
            p2 += __shfl_xor_sync(0xFFFFFFFFu, p2, 2);
            if ((lid & 3) == 0) {
                const int rbase = wm * 32 + mt * 16 + rl;
                sPart[wn * TILE_M + rbase]     = p1;
                sPart[wn * TILE_M + rbase + 8] = p2;
            }
        }
        __syncthreads();

        if (tid < TILE_M) {
            const int e = tile0 + tid;
            if (e < E_TOTAL) out[e] = sPart[tid] + sPart[TILE_M + tid] + bias2;
        }
    }
}

// ============================ launch ============================
extern "C" void kernel_launch(void* const* d_in, const int* in_sizes, int n_in,
                              void* d_out, int out_size) {
    (void)in_sizes; (void)n_in; (void)out_size;
    const int*   src         = (const int*)d_in[0];
    const int*   dst         = (const int*)d_in[1];
    const float* t           = (const float*)d_in[2];
    const float* edge_attr   = (const float*)d_in[3];
    const float* memory      = (const float*)d_in[4];
    const float* last_update = (const float*)d_in[5];
    const float* time_w      = (const float*)d_in[6];
    const float* time_b      = (const float*)d_in[7];
    const float* w1          = (const float*)d_in[8];
    const float* b1          = (const float*)d_in[9];
    const float* w2          = (const float*)d_in[10];
    const float* b2          = (const float*)d_in[11];
    float* out = (float*)d_out;

    prep_w1_kernel<<<(K_PAD * HID + 255) / 256, 256>>>(w1);

    cudaFuncSetAttribute(tgn_growth_kernel,
                         cudaFuncAttributeMaxDynamicSharedMemorySize, SMEM_DYN);
    tgn_growth_kernel<<<NUM_CTAS, NTHREADS, SMEM_DYN>>>(
        src, dst, t, edge_attr, memory, last_update, time_w, time_b, b1, w2, b2, out);
}

// round 14
// speedup vs baseline: 1.9389x; 1.9389x over previous
#include <cuda_runtime.h>
#include <cuda_fp16.h>
#include <cstdint>

// ============================ problem constants ============================
static constexpr int E_TOTAL = 500000;
static constexpr int MEM_D   = 100;
static constexpr int EDGE_D  = 172;
static constexpr int HID     = 128;
static constexpr int IN_D    = 472;   // 100 + 100 + 100 + 172
static constexpr int K_PAD   = 480;
static constexpr int KCHUNK  = 16;
static constexpr int NCHUNK  = K_PAD / KCHUNK;    // 30
static constexpr int TILE_M  = 256;               // edges per tile
static constexpr int NTHREADS = 512;              // 16 warps, each 16 rows x 128 cols
static constexpr int NUM_CTAS = 152;              // persistent: one per SM
static constexpr int NUM_TILES = (E_TOTAL + TILE_M - 1) / TILE_M;  // 1954

static constexpr int B_LD = 136;                  // halves; 272B row stride

// ============================ smem layout (bytes, dynamic) ============================
static constexpr int SO_B    = 0;                             // full W1: 480 x B_LD halves
static constexpr int B_BYTES = K_PAD * B_LD * 2;              // 130560
static constexpr int SO_SRC  = SO_B + B_BYTES;                // int[256]
static constexpr int SO_DST  = SO_SRC + TILE_M * 4;
static constexpr int SO_EOF  = SO_DST + TILE_M * 4;
static constexpr int SO_DT   = SO_EOF + TILE_M * 4;           // float[256]
static constexpr int SO_B1   = SO_DT  + TILE_M * 4;           // float[128]
static constexpr int SO_W2   = SO_B1  + HID * 4;              // float[128]
static constexpr int SMEM_DYN = SO_W2 + HID * 4;              // 135680 B

// fp16 w1, row-major [K_PAD x HID], zero rows 472..479.
__device__ __align__(16) __half g_w1_f16[K_PAD * HID];

__device__ __forceinline__ uint32_t smem_u32(const void* p) {
    uint32_t a;
    asm("{ .reg .u64 t; cvta.to.shared.u64 t, %1; cvt.u32.u64 %0, t; }" : "=r"(a) : "l"(p));
    return a;
}

// Accurate cos for |x| up to ~1e4: Cody-Waite 2-step reduction + MUFU cos.
__device__ __forceinline__ float fast_cos(float x) {
    float k = rintf(x * 0.15915494309189535f);
    float y = fmaf(-k, 6.28125f, x);
    y = fmaf(-k, 1.9353072e-3f, y);
    return __cosf(y);
}

__device__ __forceinline__ void mma16816(float d[4], const uint32_t a[4],
                                         uint32_t b0, uint32_t b1) {
    asm volatile(
        "mma.sync.aligned.m16n8k16.row.col.f32.f16.f16.f32 "
        "{%0,%1,%2,%3}, {%4,%5,%6,%7}, {%8,%9}, {%0,%1,%2,%3};"
        : "+f"(d[0]), "+f"(d[1]), "+f"(d[2]), "+f"(d[3])
        : "r"(a[0]), "r"(a[1]), "r"(a[2]), "r"(a[3]), "r"(b0), "r"(b1));
}

// ============================ prologue: w1 -> fp16 ============================
__global__ void prep_w1_kernel(const float* __restrict__ w1) {
    int idx = blockIdx.x * blockDim.x + threadIdx.x;   // 0 .. 480*128-1
    int k = idx / HID;
    float v = (k < IN_D) ? w1[idx] : 0.0f;
    g_w1_f16[idx] = __float2half(v);
}

// ============================ main kernel ============================
__global__ void __launch_bounds__(NTHREADS, 1)
tgn_growth_kernel(const int* __restrict__ src, const int* __restrict__ dst,
                  const float* __restrict__ t, const float* __restrict__ edge_attr,
                  const float* __restrict__ memory, const float* __restrict__ last_update,
                  const float* __restrict__ time_w, const float* __restrict__ time_b,
                  const float* __restrict__ b1, const float* __restrict__ w2,
                  const float* __restrict__ b2, float* __restrict__ out) {
    extern __shared__ __align__(16) char smem[];
    int*   sSrc = (int*)(smem + SO_SRC);
    int*   sDst = (int*)(smem + SO_DST);
    int*   sEof = (int*)(smem + SO_EOF);
    float* sDt  = (float*)(smem + SO_DT);
    float* sB1f = (float*)(smem + SO_B1);
    float* sW2f = (float*)(smem + SO_W2);

    const int tid = threadIdx.x;
    const int wid = tid >> 5;          // 0..15: warp owns rows [16*wid, 16*wid+16)
    const int lid = tid & 31;
    const int rl  = lid >> 2;          // 0..7
    const int c0  = (lid & 3) * 2;     // 0,2,4,6

    // ---- load full W1 into smem once (cp.async, one wait) ----
    const uint32_t bBase = smem_u32(smem + SO_B);
    for (int i = tid; i < K_PAD * 16; i += NTHREADS) {    // 480 rows x 16 16B-segs
        const int row = i >> 4, seg = i & 15;
        const __half* gsrc = g_w1_f16 + row * HID + seg * 8;
        asm volatile("cp.async.cg.shared.global [%0], [%1], 16;"
                     :: "r"(bBase + (uint32_t)(row * B_LD + seg * 8) * 2), "l"(gsrc)
                     : "memory");
    }
    asm volatile("cp.async.commit_group;" ::: "memory");
    if (tid < HID) { sB1f[tid] = b1[tid]; sW2f[tid] = w2[tid]; }
    const float bias2 = b2[0];
    asm volatile("cp.async.wait_group 0;" ::: "memory");
    __syncthreads();

    // ldmatrix.x4 lane address: lanes 0-15 -> 16 k-rows, lanes 16-31 -> +8 cols.
    const uint32_t ldmBase =
        bBase + (uint32_t)((((lid & 15) * B_LD) + ((lid >> 4) * 8)) * 2);

    // ---- persistent tile loop ----
    for (int tile = blockIdx.x; tile < NUM_TILES; tile += NUM_CTAS) {
        const int tile0 = tile * TILE_M;

        __syncthreads();   // all warps done with previous tile (offsets in regs)
        if (tid < TILE_M) {
            int e  = tile0 + tid;
            int ec = (e < E_TOTAL) ? e : (E_TOTAL - 1);
            int s  = src[ec];
            sSrc[tid] = s * MEM_D;
            sDst[tid] = dst[ec] * MEM_D;
            sDt[tid]  = t[ec] - last_update[s];
            sEof[tid] = ec * EDGE_D;
        }
        __syncthreads();

        // per-thread rows: wid*16 + rl and +8
        int srcO[2], dstO[2], eofO[2];
        float dtv[2];
        #pragma unroll
        for (int i = 0; i < 2; ++i) {
            const int r = wid * 16 + i * 8 + rl;
            srcO[i] = sSrc[r]; dstO[i] = sDst[r]; eofO[i] = sEof[r]; dtv[i] = sDt[r];
        }

        // 2-deep register prefetch: pre[slot][i=row][g=kgroup]
        float2 pre[2][4];
        auto gatherChunk = [&](int c, int slot) {
            const int kb = c * KCHUNK;
            #pragma unroll
            for (int i = 0; i < 2; ++i) {
                #pragma unroll
                for (int g = 0; g < 2; ++g) {
                    const int k = kb + c0 + g * 8;   // even; pairs never straddle regions
                    float2 v;
                    if (k < MEM_D) {
                        v = *reinterpret_cast<const float2*>(memory + srcO[i] + k);
                    } else if (k < 2 * MEM_D) {
                        v = *reinterpret_cast<const float2*>(memory + dstO[i] + (k - MEM_D));
                    } else if (k < 300) {
                        float2 tw2 = *reinterpret_cast<const float2*>(time_w + (k - 200));
                        float2 tb2 = *reinterpret_cast<const float2*>(time_b + (k - 200));
                        v.x = fast_cos(fmaf(dtv[i], tw2.x, tb2.x));
                        v.y = fast_cos(fmaf(dtv[i], tw2.y, tb2.y));
                    } else if (k < IN_D) {
                        v = *reinterpret_cast<const float2*>(edge_attr + eofO[i] + (k - 300));
                    } else {
                        v = make_float2(0.0f, 0.0f);
                    }
                    pre[slot][i * 2 + g] = v;
                }
            }
        };

        float acc[16][4];
        #pragma unroll
        for (int nt = 0; nt < 16; ++nt)
            #pragma unroll
            for (int q = 0; q < 4; ++q) acc[nt][q] = 0.0f;

        gatherChunk(0, 0);
        gatherChunk(1, 1);

        // ---- barrier-free mainloop (B resident; 2 chunks of LDGs in flight) ----
        #pragma unroll
        for (int c = 0; c < NCHUNK; ++c) {
            const int slot = c & 1;
            // A fragments from prefetched regs
            uint32_t aR[4];
            #pragma unroll
            for (int g = 0; g < 2; ++g)
                #pragma unroll
                for (int i = 0; i < 2; ++i) {
                    float2 v = pre[slot][i * 2 + g];
                    __half2 h2 = __floats2half2_rn(v.x, v.y);
                    aR[g * 2 + i] = *reinterpret_cast<uint32_t*>(&h2);
                }

            if (c + 2 < NCHUNK) gatherChunk(c + 2, slot);   // refill freed slot

            const uint32_t la = ldmBase + (uint32_t)(c * KCHUNK * B_LD * 2);
            #pragma unroll
            for (int ntp = 0; ntp < 8; ++ntp) {
                uint32_t b0, b1r, b2r, b3r;
                asm volatile(
                    "ldmatrix.sync.aligned.m8n8.x4.trans.shared.b16 {%0,%1,%2,%3}, [%4];"
                    : "=r"(b0), "=r"(b1r), "=r"(b2r), "=r"(b3r) : "r"(la + ntp * 32));
                mma16816(acc[2 * ntp],     aR, b0, b1r);
                mma16816(acc[2 * ntp + 1], aR, b2r, b3r);
            }
        }

        // ---- epilogue: bias + ReLU + dot(w2), fully in-warp ----
        float p1 = 0.0f, p2 = 0.0f;   // rows rl, rl+8
        #pragma unroll
        for (int nt = 0; nt < 16; ++nt) {
            const int n0 = nt * 8 + c0;
            float2 bb = *reinterpret_cast<const float2*>(&sB1f[n0]);
            float2 ww = *reinterpret_cast<const float2*>(&sW2f[n0]);
            const float* d = acc[nt];
            p1 = fmaf(fmaxf(d[0] + bb.x, 0.0f), ww.x, p1);
            p1 = fmaf(fmaxf(d[1] + bb.y, 0.0f), ww.y, p1);
            p2 = fmaf(fmaxf(d[2] + bb.x, 0.0f), ww.x, p2);
            p2 = fmaf(fmaxf(d[3] + bb.y, 0.0f), ww.y, p2);
        }
        p1 += __shfl_xor_sync(0xFFFFFFFFu, p1, 1);
        p1 += __shfl_xor_sync(0xFFFFFFFFu, p1, 2);
        p2 += __shfl_xor_sync(0xFFFFFFFFu, p2, 1);
        p2 += __shfl_xor_sync(0xFFFFFFFFu, p2, 2);
        if ((lid & 3) == 0) {
            const int e1 = tile0 + wid * 16 + rl;
            const int e2 = e1 + 8;
            if (e1 < E_TOTAL) out[e1] = p1 + bias2;
            if (e2 < E_TOTAL) out[e2] = p2 + bias2;
        }
    }
}

// ============================ launch ============================
extern "C" void kernel_launch(void* const* d_in, const int* in_sizes, int n_in,
                              void* d_out, int out_size) {
    (void)in_sizes; (void)n_in; (void)out_size;
    const int*   src         = (const int*)d_in[0];
    const int*   dst         = (const int*)d_in[1];
    const float* t           = (const float*)d_in[2];
    const float* edge_attr   = (const float*)d_in[3];
    const float* memory      = (const float*)d_in[4];
    const float* last_update = (const float*)d_in[5];
    const float* time_w      = (const float*)d_in[6];
    const float* time_b      = (const float*)d_in[7];
    const float* w1          = (const float*)d_in[8];
    const float* b1          = (const float*)d_in[9];
    const float* w2          = (const float*)d_in[10];
    const float* b2          = (const float*)d_in[11];
    float* out = (float*)d_out;

    prep_w1_kernel<<<(K_PAD * HID + 255) / 256, 256>>>(w1);

    cudaFuncSetAttribute(tgn_growth_kernel,
                         cudaFuncAttributeMaxDynamicSharedMemorySize, SMEM_DYN);
    tgn_growth_kernel<<<NUM_CTAS, NTHREADS, SMEM_DYN>>>(
        src, dst, t, edge_attr, memory, last_update, time_w, time_b, b1, w2, b2, out);
}